// round 1
// baseline (speedup 1.0000x reference)
#include <cuda_runtime.h>
#include <cuda_bf16.h>

// GenderAwareCrossEntropyLoss: per-row CE(log_softmax, label) * weight +
// 5.0 penalty when argmax class is invalid for (g1,g2); mean over N rows.
//
// HBM-bound streaming reduction. Each thread processes 4 consecutive rows so
// the 7-float rows coalesce into 7 aligned float4 loads per thread.

#define ROWS_PER_THREAD 4
#define BLOCK_THREADS   256
#define MAX_BLOCKS      8192

__device__ float g_partials[MAX_BLOCKS];

// VALID table packed: for g = g1*2+g2, valid-class bitmask (7 bits each):
//  g=0 (0,0): classes {1,4}  -> 0b0010010 = 18
//  g=1 (0,1): classes {0,3,6}-> 0b1001001 = 73
//  g=2 (1,0): classes {0,3,6}-> 73
//  g=3 (1,1): classes {2,5}  -> 0b0100100 = 36
#define VALID_PACKED ((18u) | (73u << 7) | (73u << 14) | (36u << 21))

__global__ __launch_bounds__(BLOCK_THREADS)
void gace_main_kernel(const float* __restrict__ logits,
                      const float* __restrict__ class_weights,
                      const int*   __restrict__ labels,
                      const int*   __restrict__ gender,
                      int nrows, int ngroups)
{
    // Preload the 7 class weights once (L1-resident const-like data).
    float cw[7];
#pragma unroll
    for (int c = 0; c < 7; c++) cw[c] = __ldg(&class_weights[c]);

    float acc = 0.0f;

    // Grid-stride over groups of 4 rows.
    for (int grp = blockIdx.x * BLOCK_THREADS + threadIdx.x;
         grp < ngroups;
         grp += gridDim.x * BLOCK_THREADS)
    {
        int r0 = grp * ROWS_PER_THREAD;

        if (r0 + ROWS_PER_THREAD <= nrows) {
            // ---- front-batched wide loads (max MLP) ----
            float4 lv[7];
            const float4* lp = reinterpret_cast<const float4*>(logits + (size_t)r0 * 7);
#pragma unroll
            for (int i = 0; i < 7; i++) lv[i] = lp[i];

            int4 lab4 = *reinterpret_cast<const int4*>(labels + r0);
            const int4* gp = reinterpret_cast<const int4*>(gender + (size_t)r0 * 2);
            int4 gA = gp[0];
            int4 gB = gp[1];

            const float* x = reinterpret_cast<const float*>(lv);  // 28 floats, fully unrolled below
            int   labs[4] = { lab4.x, lab4.y, lab4.z, lab4.w };
            int   gidx[4] = { gA.x * 2 + gA.y, gA.z * 2 + gA.w,
                              gB.x * 2 + gB.y, gB.z * 2 + gB.w };

#pragma unroll
            for (int j = 0; j < 4; j++) {
                float v0 = x[j*7+0], v1 = x[j*7+1], v2 = x[j*7+2], v3 = x[j*7+3];
                float v4 = x[j*7+4], v5 = x[j*7+5], v6 = x[j*7+6];

                // argmax (first max wins, matching jnp.argmax) + max
                float m = v0; int am = 0;
                if (v1 > m) { m = v1; am = 1; }
                if (v2 > m) { m = v2; am = 2; }
                if (v3 > m) { m = v3; am = 3; }
                if (v4 > m) { m = v4; am = 4; }
                if (v5 > m) { m = v5; am = 5; }
                if (v6 > m) { m = v6; am = 6; }

                float s = __expf(v0 - m) + __expf(v1 - m) + __expf(v2 - m)
                        + __expf(v3 - m) + __expf(v4 - m) + __expf(v5 - m)
                        + __expf(v6 - m);

                // gather x[label] without dynamic register indexing
                int lab = labs[j];
                float xl = v0;
                xl = (lab == 1) ? v1 : xl;
                xl = (lab == 2) ? v2 : xl;
                xl = (lab == 3) ? v3 : xl;
                xl = (lab == 4) ? v4 : xl;
                xl = (lab == 5) ? v5 : xl;
                xl = (lab == 6) ? v6 : xl;

                float w = cw[0];
                w = (lab == 1) ? cw[1] : w;
                w = (lab == 2) ? cw[2] : w;
                w = (lab == 3) ? cw[3] : w;
                w = (lab == 4) ? cw[4] : w;
                w = (lab == 5) ? cw[5] : w;
                w = (lab == 6) ? cw[6] : w;

                float ce = __logf(s) - (xl - m);   // -logp[label]

                unsigned bit = (VALID_PACKED >> (gidx[j] * 7 + am)) & 1u;
                float pen = bit ? 0.0f : 5.0f;

                acc += w * ce + pen;
            }
        } else {
            // tail (not hit for N=4M, kept for generality)
            for (int r = r0; r < nrows; r++) {
                float v[7];
#pragma unroll
                for (int c = 0; c < 7; c++) v[c] = logits[(size_t)r * 7 + c];
                float m = v[0]; int am = 0;
#pragma unroll
                for (int c = 1; c < 7; c++) if (v[c] > m) { m = v[c]; am = c; }
                float s = 0.0f;
#pragma unroll
                for (int c = 0; c < 7; c++) s += __expf(v[c] - m);
                int lab = labels[r];
                float xl = v[0], w = cw[0];
#pragma unroll
                for (int c = 1; c < 7; c++) {
                    xl = (lab == c) ? v[c] : xl;
                    w  = (lab == c) ? cw[c] : w;
                }
                int g = gender[(size_t)r * 2] * 2 + gender[(size_t)r * 2 + 1];
                unsigned bit = (VALID_PACKED >> (g * 7 + am)) & 1u;
                acc += w * (__logf(s) - (xl - m)) + (bit ? 0.0f : 5.0f);
            }
        }
    }

    // ---- deterministic block reduction ----
    __shared__ float wsum[BLOCK_THREADS / 32];
    int lane = threadIdx.x & 31;
    int wid  = threadIdx.x >> 5;
#pragma unroll
    for (int o = 16; o > 0; o >>= 1)
        acc += __shfl_down_sync(0xffffffffu, acc, o);
    if (lane == 0) wsum[wid] = acc;
    __syncthreads();
    if (wid == 0) {
        float v = (lane < BLOCK_THREADS / 32) ? wsum[lane] : 0.0f;
#pragma unroll
        for (int o = 4; o > 0; o >>= 1)
            v += __shfl_down_sync(0xffffffffu, v, o);
        if (lane == 0) g_partials[blockIdx.x] = v;
    }
}

__global__ void gace_reduce_kernel(float* __restrict__ out, int nblocks, int nrows)
{
    __shared__ double sm[256];
    double s = 0.0;
    for (int i = threadIdx.x; i < nblocks; i += 256)
        s += (double)g_partials[i];
    sm[threadIdx.x] = s;
    __syncthreads();
#pragma unroll
    for (int st = 128; st > 0; st >>= 1) {
        if (threadIdx.x < st) sm[threadIdx.x] += sm[threadIdx.x + st];
        __syncthreads();
    }
    if (threadIdx.x == 0)
        out[0] = (float)(sm[0] / (double)nrows);
}

extern "C" void kernel_launch(void* const* d_in, const int* in_sizes, int n_in,
                              void* d_out, int out_size)
{
    const float* logits        = (const float*)d_in[0];
    const float* class_weights = (const float*)d_in[1];
    const int*   labels        = (const int*)d_in[2];
    const int*   gender        = (const int*)d_in[3];
    float*       out           = (float*)d_out;

    int nrows   = in_sizes[2];                       // N (labels element count)
    int ngroups = (nrows + ROWS_PER_THREAD - 1) / ROWS_PER_THREAD;
    int blocks  = (ngroups + BLOCK_THREADS - 1) / BLOCK_THREADS;
    if (blocks > MAX_BLOCKS) blocks = MAX_BLOCKS;

    gace_main_kernel<<<blocks, BLOCK_THREADS>>>(logits, class_weights, labels,
                                                gender, nrows, ngroups);
    gace_reduce_kernel<<<1, 256>>>(out, blocks, nrows);
}